// round 16
// baseline (speedup 1.0000x reference)
#include <cuda_runtime.h>
#include <cuda_bf16.h>
#include <cstdint>

// Problem constants
#define SS     512
#define BB     32
#define HH     512
#define NSPAN  2048
#define DD     256
#define LMAXC  16
#define LDIMC  32
#define VV     50257
#define KP     2080
#define KC     1056
#define NROWS  4096
#define NTV    393            // ceil(50257/128) vocab tiles
#define NVPAD  (NTV*128)      // 50304 padded vocab rows
#define NEG_BIG -1e30f

// int8 scaling
#define SCALE_A 127.0f
#define SCALE_W 1270.0f
#define INV_SCALE (1.0f / (127.0f * 1270.0f))
#define SX      28.0f
#define SWF     1270.0f
#define INV_F   (1.0f / (28.0f * 1270.0f))

// ---------------- scratch (device globals; no allocs allowed) ----------------
__device__ __align__(16) uint8_t g_X8[NSPAN * KP];
__device__ __align__(16) uint8_t g_Wc8[DD * KC];
__device__ __align__(16) uint8_t g_Wp8[DD * KP];
__device__ float g_feats[NROWS * DD];
__device__ __align__(16) uint8_t g_A8[NROWS * DD];
__device__ __align__(16) uint8_t g_W8[(size_t)NVPAD * DD];
__device__ float g_pm[NROWS * NTV];
__device__ float g_ps[NROWS * NTV];
__device__ float g_focal[NROWS];

// ---------------------------------------------------------------------------
// helpers
// ---------------------------------------------------------------------------
__device__ __forceinline__ uint32_t pack_s8x4(float a, float b, float c, float d) {
    int ia = __float2int_rn(fminf(fmaxf(a, -127.f), 127.f));
    int ib = __float2int_rn(fminf(fmaxf(b, -127.f), 127.f));
    int ic = __float2int_rn(fminf(fmaxf(c, -127.f), 127.f));
    int id = __float2int_rn(fminf(fmaxf(d, -127.f), 127.f));
    return (uint32_t)(ia & 0xFF) | ((uint32_t)(ib & 0xFF) << 8) |
           ((uint32_t)(ic & 0xFF) << 16) | ((uint32_t)(id & 0xFF) << 24);
}
__device__ __forceinline__ void mma_s8(int* c, uint32_t a0, uint32_t a1,
                                       uint32_t a2, uint32_t a3,
                                       uint32_t b0, uint32_t b1) {
    asm volatile("mma.sync.aligned.m16n8k32.row.col.s32.s8.s8.s32 "
        "{%0,%1,%2,%3}, {%4,%5,%6,%7}, {%8,%9}, {%0,%1,%2,%3};"
        : "+r"(c[0]), "+r"(c[1]), "+r"(c[2]), "+r"(c[3])
        : "r"(a0), "r"(a1), "r"(a2), "r"(a3), "r"(b0), "r"(b1));
}
__device__ __forceinline__ void ldm_x4(uint32_t& r0, uint32_t& r1,
                                       uint32_t& r2, uint32_t& r3, uint32_t addr) {
    asm volatile("ldmatrix.sync.aligned.m8n8.x4.shared.b16 {%0,%1,%2,%3}, [%4];"
        : "=r"(r0), "=r"(r1), "=r"(r2), "=r"(r3) : "r"(addr));
}
__device__ __forceinline__ uint32_t smem_u32(const void* p) {
    uint32_t a;
    asm("{ .reg .u64 t; cvta.to.shared.u64 t, %1; cvt.u32.u64 %0, t; }" : "=r"(a) : "l"(p));
    return a;
}
__device__ __forceinline__ void cp16(uint32_t saddr, const void* gaddr) {
    asm volatile("cp.async.cg.shared.global [%0], [%1], 16;" :: "r"(saddr), "l"(gaddr) : "memory");
}
#define CP_COMMIT() asm volatile("cp.async.commit_group;" ::: "memory")
#define CP_WAIT(n)  asm volatile("cp.async.wait_group %0;" :: "n"(n) : "memory")

// ---------------------------------------------------------------------------
// 1) Gather span features directly as s8 into g_X8 [N, 2080]
// ---------------------------------------------------------------------------
__global__ void gather_kernel(const float* __restrict__ fwd,
                              const float* __restrict__ bwd,
                              const int* __restrict__ begins,
                              const int* __restrict__ ends,
                              const int* __restrict__ bids,
                              const float* __restrict__ len_emb) {
    int n = blockIdx.x;
    int t = threadIdx.x;
    int b = bids[n], bg = begins[n], en = ends[n];
    int len = min(en - bg, LMAXC) - 1;
    uint32_t* X = (uint32_t*)(g_X8 + (size_t)n * KP);
    if (t < 8) {
        const float* le = len_emb + len * LDIMC + t * 4;
        X[t] = pack_s8x4(le[0] * SX, le[1] * SX, le[2] * SX, le[3] * SX);
    }
    const float* fb = fwd + ((size_t)(bg - 1) * BB + b) * HH;
    const float* fe = fwd + ((size_t)(en - 1) * BB + b) * HH;
    const float* be = bwd + ((size_t)en * BB + b) * HH;
    const float* bb = bwd + ((size_t)bg * BB + b) * HH;
    for (int idx = t; idx < 512; idx += 256) {
        int sec = idx >> 7, grp = idx & 127;
        const float* s = (sec == 0) ? fb : (sec == 1) ? fe : (sec == 2) ? be : bb;
        float4 v = *(const float4*)(s + grp * 4);
        X[8 + idx] = pack_s8x4(v.x * SX, v.y * SX, v.z * SX, v.w * SX);
    }
}

// ---------------------------------------------------------------------------
// 2) Convert W_ctx + W_phr fp32 -> s8 (x1270)
// ---------------------------------------------------------------------------
#define WC_U4 (DD * KC / 16)
#define WP_U4 (DD * KP / 16)
__global__ __launch_bounds__(256) void convert_wfeat(const float* __restrict__ Wc,
                                                     const float* __restrict__ Wp) {
    int idx = blockIdx.x * 256 + threadIdx.x;
    const float* src;
    uint8_t* dst;
    if (idx < WC_U4) { src = Wc + idx * 16; dst = g_Wc8 + idx * 16; }
    else {
        int j = idx - WC_U4;
        if (j >= WP_U4) return;
        src = Wp + j * 16; dst = g_Wp8 + j * 16;
    }
    const float4* p = (const float4*)src;
    float4 w0 = p[0], w1 = p[1], w2 = p[2], w3 = p[3];
    uint4 u;
    u.x = pack_s8x4(w0.x * SWF, w0.y * SWF, w0.z * SWF, w0.w * SWF);
    u.y = pack_s8x4(w1.x * SWF, w1.y * SWF, w1.z * SWF, w1.w * SWF);
    u.z = pack_s8x4(w2.x * SWF, w2.y * SWF, w2.z * SWF, w2.w * SWF);
    u.w = pack_s8x4(w3.x * SWF, w3.y * SWF, w3.z * SWF, w3.w * SWF);
    *(uint4*)dst = u;
}

// ---------------------------------------------------------------------------
// 3) Convert W_lab fp32 -> s8 (x1270), padded
// ---------------------------------------------------------------------------
__global__ __launch_bounds__(256) void convert_wlab(const float* __restrict__ W) {
    int idx = blockIdx.x * 256 + threadIdx.x;
    int rg = idx >> 4;
    int kc = (idx & 15) << 4;
    if (rg >= NVPAD) return;
    float4 w0 = make_float4(0,0,0,0), w1 = w0, w2 = w0, w3 = w0;
    if (rg < VV) {
        const float4* p = (const float4*)(W + (size_t)rg * DD + kc);
        w0 = p[0]; w1 = p[1]; w2 = p[2]; w3 = p[3];
    }
    uint4 u;
    u.x = pack_s8x4(w0.x * SCALE_W, w0.y * SCALE_W, w0.z * SCALE_W, w0.w * SCALE_W);
    u.y = pack_s8x4(w1.x * SCALE_W, w1.y * SCALE_W, w1.z * SCALE_W, w1.w * SCALE_W);
    u.z = pack_s8x4(w2.x * SCALE_W, w2.y * SCALE_W, w2.z * SCALE_W, w2.w * SCALE_W);
    u.w = pack_s8x4(w3.x * SCALE_W, w3.y * SCALE_W, w3.z * SCALE_W, w3.w * SCALE_W);
    *(uint4*)&g_W8[(size_t)rg * DD + kc] = u;
}

// ---------------------------------------------------------------------------
// 4) s8 IMMA feature GEMM: both branches in ONE launch (256 CTAs).
//    Impl is compile-time templated (static NIT), smem shared via params.
// ---------------------------------------------------------------------------
#define PIT8 12
#define ROWB (PIT8*4)
#define FSTG (64 * PIT8)

template <bool IS_CTX, int KTOT>
__device__ __forceinline__ void feat_impl(uint32_t* fsm, float* bias_s,
                                          const float* __restrict__ bias,
                                          int bid, int row_off) {
    constexpr int NIT = KTOT / 32;
    int rb = (bid >> 2) * 64;
    int cb = (bid & 3) * 64;
    const uint8_t* gW = IS_CTX ? g_Wc8 : g_Wp8;

    int tid = threadIdx.x, lane = tid & 31, wid = tid >> 5;
    int g = lane >> 2, t4 = lane & 3;
    int wr = wid & 1, wc = wid >> 1;
    if (tid < 64) bias_s[tid] = bias[cb + tid];

    uint32_t* As = fsm;
    uint32_t* Bs = fsm + 3 * FSTG;
    uint32_t asb = smem_u32(As), bsb = smem_u32(Bs);
    int srow = tid >> 1, schk = tid & 1;
    const uint8_t* gXrow = g_X8 + (size_t)(rb + srow) * KP;
    const uint8_t* gWrow = gW + (size_t)(cb + srow) * KTOT;

    uint32_t a_loff = (uint32_t)(wr * 32 + (lane & 15)) * ROWB + (uint32_t)(lane >> 4) * 16;
    uint32_t b_loff = (uint32_t)(wc * 32 + (lane & 7) + ((lane >> 4) << 3)) * ROWB
                    + (uint32_t)((lane >> 3) & 1) * 16;

    int acc[2][4][4] = {};

#define FLOAD(stg, k0) do { \
    int kc_ = (k0); \
    int srcA = IS_CTX ? (kc_ < 544 ? kc_ : kc_ + 512) : kc_; \
    cp16(asb + ((stg) * FSTG + srow * PIT8 + schk * 4) * 4, gXrow + srcA + schk * 16); \
    cp16(bsb + ((stg) * FSTG + srow * PIT8 + schk * 4) * 4, gWrow + kc_ + schk * 16); \
} while (0)

    FLOAD(0, 0);  CP_COMMIT();
    FLOAD(1, 32); CP_COMMIT();

    for (int it = 0; it < NIT; it++) {
        CP_WAIT(1);
        __syncthreads();
        if (it + 2 < NIT) FLOAD((it + 2) % 3, (it + 2) * 32);
        CP_COMMIT();

        int cur = it % 3;
        uint32_t ab = asb + (uint32_t)cur * (FSTG * 4) + a_loff;
        uint32_t bb2 = bsb + (uint32_t)cur * (FSTG * 4) + b_loff;
        uint32_t af[2][4], bf[4][2];
        ldm_x4(af[0][0], af[0][1], af[0][2], af[0][3], ab);
        ldm_x4(af[1][0], af[1][1], af[1][2], af[1][3], ab + 16 * ROWB);
        ldm_x4(bf[0][0], bf[0][1], bf[1][0], bf[1][1], bb2);
        ldm_x4(bf[2][0], bf[2][1], bf[3][0], bf[3][1], bb2 + 16 * ROWB);
#pragma unroll
        for (int mt = 0; mt < 2; mt++)
#pragma unroll
            for (int nt = 0; nt < 4; nt++)
                mma_s8(acc[mt][nt], af[mt][0], af[mt][1], af[mt][2], af[mt][3],
                       bf[nt][0], bf[nt][1]);
        __syncthreads();
    }
#undef FLOAD

#pragma unroll
    for (int mt = 0; mt < 2; mt++)
#pragma unroll
        for (int h = 0; h < 2; h++) {
            int rl = wr * 32 + mt * 16 + h * 8 + g;
            int r = row_off + rb + rl;
#pragma unroll
            for (int nt = 0; nt < 4; nt++) {
                int col = wc * 32 + nt * 8 + t4 * 2;
                float z0 = fmaf((float)acc[mt][nt][h * 2 + 0], INV_F, bias_s[col]);
                float z1 = fmaf((float)acc[mt][nt][h * 2 + 1], INV_F, bias_s[col + 1]);
                float f0 = tanhf(z0), f1 = tanhf(z1);
                int cg = cb + col;
                *(float2*)&g_feats[r * DD + cg] = make_float2(f0, f1);
                int i0 = __float2int_rn(fminf(fmaxf(f0 * SCALE_A, -127.f), 127.f));
                int i1 = __float2int_rn(fminf(fmaxf(f1 * SCALE_A, -127.f), 127.f));
                *(uint16_t*)&g_A8[r * DD + cg] =
                    (uint16_t)((i0 & 0xFF) | ((i1 & 0xFF) << 8));
            }
        }
}

__global__ void __launch_bounds__(128) feat_gemm_all(const float* __restrict__ bc,
                                                     const float* __restrict__ bp) {
    __shared__ uint32_t fsm[6 * FSTG];
    __shared__ float bias_s[64];
    int bid = blockIdx.x;
    if (bid < 128) feat_impl<true,  KC>(fsm, bias_s, bc, bid, 0);
    else           feat_impl<false, KP>(fsm, bias_s, bp, bid - 128, NSPAN);
}

// ---------------------------------------------------------------------------
// 5) s8 IMMA big GEMM + fused softmax partials.
//    BM 64, acc 32 regs, 3 CTAs/SM: deeper epilogue/mainloop overlap.
//    8 warps 2(m) x 4(n), warp tile 32x32.
// ---------------------------------------------------------------------------
#define BM 64
#define BN 128
#define BK 32
#define ASTG (BM * PIT8)      // 768 words / stage
#define BSTG (BN * PIT8)      // 1536 words / stage
#define NSTAGE 3
#define SMEM_BG ((NSTAGE*(ASTG+BSTG))*4 + 128*4 + 64*4*4*2)

__global__ void __launch_bounds__(256, 3) big_gemm_mma(const float* __restrict__ blab) {
    extern __shared__ uint32_t dsm[];
    uint32_t* As = dsm;
    uint32_t* Bs = dsm + NSTAGE * ASTG;
    float* bias_s = (float*)(dsm + NSTAGE * (ASTG + BSTG));
    float* pm_s = bias_s + 128;                           // [64][4]
    float* ps_s = pm_s + 256;

    int tid  = threadIdx.x;
    int wid  = tid >> 5, lane = tid & 31;
    int g    = lane >> 2, t4 = lane & 3;
    int wr   = wid & 1, wc = wid >> 1;        // warp grid 2(m) x 4(n), warp 32x32
    int vt   = blockIdx.x, rt = blockIdx.y;
    int vb   = vt * 128;

    if (tid < 128) {
        int v = vb + tid;
        bias_s[tid] = (v < VV) ? blab[v] : 0.f;
    }

    const uint8_t* gA = g_A8 + (size_t)rt * BM * DD;
    const uint8_t* gB = g_W8 + (size_t)vb * DD;
    uint32_t asb = smem_u32(As);
    uint32_t bsb = smem_u32(Bs);

    int srow = tid >> 1, schk = tid & 1;      // B: 128 rows x 2; A: tid<128 only

    uint32_t a_loff = (uint32_t)(wr * 32 + (lane & 15)) * ROWB + (uint32_t)(lane >> 4) * 16;
    uint32_t b_loff = (uint32_t)(wc * 32 + (lane & 7) + ((lane >> 4) << 3)) * ROWB
                    + (uint32_t)((lane >> 3) & 1) * 16;

    int acc[2][4][4] = {};

#define LOAD_STAGE(stg, k0) do { \
    if (tid < 128) \
        cp16(asb + ((stg) * ASTG + srow * PIT8 + schk * 4) * 4, \
             gA + srow * DD + (k0) + schk * 16); \
    cp16(bsb + ((stg) * BSTG + srow * PIT8 + schk * 4) * 4, \
         gB + srow * DD + (k0) + schk * 16); \
} while (0)

    LOAD_STAGE(0, 0);  CP_COMMIT();
    LOAD_STAGE(1, 32); CP_COMMIT();

    for (int it = 0; it < 8; it++) {
        CP_WAIT(1);
        __syncthreads();
        if (it < 6) {
            LOAD_STAGE((it + 2) % NSTAGE, (it + 2) * BK);
        }
        CP_COMMIT();

        int cur = it % NSTAGE;
        uint32_t a_base = asb + (uint32_t)cur * (ASTG * 4) + a_loff;
        uint32_t b_base = bsb + (uint32_t)cur * (BSTG * 4) + b_loff;

        uint32_t af[2][4], bf[4][2];
        ldm_x4(af[0][0], af[0][1], af[0][2], af[0][3], a_base);
        ldm_x4(af[1][0], af[1][1], af[1][2], af[1][3], a_base + 16 * ROWB);
        ldm_x4(bf[0][0], bf[0][1], bf[1][0], bf[1][1], b_base);
        ldm_x4(bf[2][0], bf[2][1], bf[3][0], bf[3][1], b_base + 16 * ROWB);

#pragma unroll
        for (int mt = 0; mt < 2; mt++)
#pragma unroll
            for (int nt = 0; nt < 4; nt++)
                mma_s8(acc[mt][nt], af[mt][0], af[mt][1], af[mt][2], af[mt][3],
                       bf[nt][0], bf[nt][1]);
        __syncthreads();
    }

    // --- fused softmax-partial epilogue (dequant, add bias) ---
#pragma unroll
    for (int mt = 0; mt < 2; mt++) {
#pragma unroll
        for (int h = 0; h < 2; h++) {
            int rl = wr * 32 + mt * 16 + h * 8 + g;
            float v[8];
#pragma unroll
            for (int nt = 0; nt < 4; nt++) {
                int col = wc * 32 + nt * 8 + t4 * 2;
                float v0 = fmaf((float)acc[mt][nt][h * 2 + 0], INV_SCALE, bias_s[col]);
                float v1 = fmaf((float)acc[mt][nt][h * 2 + 1], INV_SCALE, bias_s[col + 1]);
                if (vb + col     >= VV) v0 = NEG_BIG;
                if (vb + col + 1 >= VV) v1 = NEG_BIG;
                v[nt * 2 + 0] = v0; v[nt * 2 + 1] = v1;
            }
            float mx = v[0];
#pragma unroll
            for (int j = 1; j < 8; j++) mx = fmaxf(mx, v[j]);
            mx = fmaxf(mx, __shfl_xor_sync(0xffffffffu, mx, 1));
            mx = fmaxf(mx, __shfl_xor_sync(0xffffffffu, mx, 2));
            float s = 0.f;
#pragma unroll
            for (int j = 0; j < 8; j++) s += __expf(v[j] - mx);
            s += __shfl_xor_sync(0xffffffffu, s, 1);
            s += __shfl_xor_sync(0xffffffffu, s, 2);
            if (t4 == 0) { pm_s[rl * 4 + wc] = mx; ps_s[rl * 4 + wc] = s; }
        }
    }
    __syncthreads();
    if (tid < 64) {
        float m0 = pm_s[tid * 4 + 0], m1 = pm_s[tid * 4 + 1];
        float m2 = pm_s[tid * 4 + 2], m3 = pm_s[tid * 4 + 3];
        float m = fmaxf(fmaxf(m0, m1), fmaxf(m2, m3));
        float s = ps_s[tid * 4 + 0] * __expf(m0 - m) + ps_s[tid * 4 + 1] * __expf(m1 - m)
                + ps_s[tid * 4 + 2] * __expf(m2 - m) + ps_s[tid * 4 + 3] * __expf(m3 - m);
        int r = rt * BM + tid;
        g_pm[r * NTV + vt] = m;
        g_ps[r * NTV + vt] = s;
    }
}

// ---------------------------------------------------------------------------
// 6) Per-row reduction: combine partials -> lse; target logit in FP32
// ---------------------------------------------------------------------------
__global__ void row_reduce(const float* __restrict__ Wlab,
                           const float* __restrict__ blab,
                           const int* __restrict__ tags) {
    int warp = (blockIdx.x * blockDim.x + threadIdx.x) >> 5;
    int lane = threadIdx.x & 31;
    if (warp >= NROWS) return;
    int r = warp;
    float m = NEG_BIG, s = 0.f;
    for (int t = lane; t < NTV; t += 32) {
        float mt = g_pm[r * NTV + t];
        float st = g_ps[r * NTV + t];
        if (mt > m) { s = s * __expf(m - mt) + st; m = mt; }
        else        { s += st * __expf(mt - m); }
    }
#pragma unroll
    for (int o = 16; o > 0; o >>= 1) {
        float mo = __shfl_xor_sync(0xffffffffu, m, o);
        float so = __shfl_xor_sync(0xffffffffu, s, o);
        if (mo > m) { s = s * __expf(m - mo) + so; m = mo; }
        else        { s += so * __expf(mo - m); }
    }
    float lse = m + __logf(s);

    int tag = tags[r & (NSPAN - 1)];
    const float* fr = g_feats + r * DD;
    const float* wr = Wlab + (size_t)tag * DD;
    float dot = 0.f;
    for (int d = lane; d < DD; d += 32) dot += fr[d] * wr[d];
#pragma unroll
    for (int o = 16; o > 0; o >>= 1) dot += __shfl_xor_sync(0xffffffffu, dot, o);

    if (lane == 0) {
        float lp = dot + blab[tag] - lse;
        float p = __expf(lp);
        float om = 1.f - p;
        g_focal[r] = -om * om * lp;
    }
}

// ---------------------------------------------------------------------------
// 7) Deterministic final sum
// ---------------------------------------------------------------------------
__global__ void final_reduce(float* __restrict__ out) {
    __shared__ float sm[1024];
    int t = threadIdx.x;
    float s = 0.f;
    for (int i = t; i < NROWS; i += 1024) s += g_focal[i];
    sm[t] = s;
    __syncthreads();
    for (int o = 512; o > 0; o >>= 1) {
        if (t < o) sm[t] += sm[t + o];
        __syncthreads();
    }
    if (t == 0) out[0] = sm[0] / ((float)NROWS + 1e-5f);
}

// ---------------------------------------------------------------------------
extern "C" void kernel_launch(void* const* d_in, const int* in_sizes, int n_in,
                              void* d_out, int out_size) {
    const float* fwd     = (const float*)d_in[0];
    const float* bwd     = (const float*)d_in[1];
    const int*   begins  = (const int*)  d_in[2];
    const int*   ends    = (const int*)  d_in[3];
    const int*   bids    = (const int*)  d_in[4];
    const int*   tags    = (const int*)  d_in[5];
    const float* len_emb = (const float*)d_in[6];
    const float* W_ctx   = (const float*)d_in[7];
    const float* b_ctx   = (const float*)d_in[8];
    const float* W_phr   = (const float*)d_in[9];
    const float* b_phr   = (const float*)d_in[10];
    const float* W_lab   = (const float*)d_in[11];
    const float* b_lab   = (const float*)d_in[12];
    float* out = (float*)d_out;

    cudaFuncSetAttribute(big_gemm_mma, cudaFuncAttributeMaxDynamicSharedMemorySize, SMEM_BG);

    gather_kernel<<<NSPAN, 256>>>(fwd, bwd, begins, ends, bids, len_emb);
    convert_wfeat<<<(WC_U4 + WP_U4 + 255) / 256, 256>>>(W_ctx, W_phr);
    convert_wlab<<<(NVPAD * 16) / 256, 256>>>(W_lab);
    feat_gemm_all<<<256, 128>>>(b_ctx, b_phr);
    big_gemm_mma<<<dim3(NTV, 64), 256, SMEM_BG>>>(b_lab);
    row_reduce<<<512, 256>>>(W_lab, b_lab, tags);
    final_reduce<<<1, 1024>>>(out);
}